// round 2
// baseline (speedup 1.0000x reference)
#include <cuda_runtime.h>

#define BB 4
#define CC 64
#define HH 128
#define WW 128
#define HWSZ 16384
#define ENCC 100
#define HO 256
#define WO 256

// scratch (static device arrays: allocation-free)
__device__ float g_comp[BB*CC*HWSZ];    // compressed features [4,64,128,128]
__device__ float g_enc[BB*ENCC*HWSZ];   // encoded logits (post-BN) [4,100,128,128]

// ---- packed f32x2 helpers (Blackwell FFMA2 path) ----
__device__ __forceinline__ unsigned long long pk2(float lo, float hi) {
    unsigned long long r;
    asm("mov.b64 %0, {%1, %2};" : "=l"(r) : "f"(lo), "f"(hi));
    return r;
}
__device__ __forceinline__ unsigned long long fma2(unsigned long long a,
                                                   unsigned long long b,
                                                   unsigned long long c) {
    unsigned long long d;
    asm("fma.rn.f32x2 %0, %1, %2, %3;" : "=l"(d) : "l"(a), "l"(b), "l"(c));
    return d;
}
__device__ __forceinline__ float2 up2(unsigned long long v) {
    float2 f;
    asm("mov.b64 {%0, %1}, %2;" : "=f"(f.x), "=f"(f.y) : "l"(v));
    return f;
}

// ============================================================================
// Kernel 1: compress = 1x1 conv (64->64) + BN + ReLU
// 128 threads/block, each thread = 1 pixel, all 64 oc in registers (32 f32x2).
// grid = BB * 128 blocks.
// ============================================================================
__global__ __launch_bounds__(128) void compress_kernel(
    const float* __restrict__ X, const float* __restrict__ Wc,
    const float* __restrict__ gamma, const float* __restrict__ beta,
    const float* __restrict__ mean,  const float* __restrict__ var)
{
    __shared__ __align__(16) float ws[64*64];   // ws[ic*64 + oc]
    __shared__ float sc[64], bs[64];
    int tid = threadIdx.x;

    for (int t = tid; t < 4096; t += 128) {
        int ic = t >> 6, oc = t & 63;
        ws[t] = Wc[oc*64 + ic];
    }
    if (tid < 64) {
        float inv = gamma[tid] * rsqrtf(var[tid] + 1e-5f);
        sc[tid] = inv;
        bs[tid] = beta[tid] - mean[tid]*inv;
    }
    __syncthreads();

    int b = blockIdx.x >> 7;                       // 128 blocks per batch
    int p = ((blockIdx.x & 127) << 7) + tid;       // pixel 0..16383
    const float* Xb = X + b*CC*HWSZ + p;

    unsigned long long acc[32];
#pragma unroll
    for (int i = 0; i < 32; i++) acc[i] = 0ULL;

#pragma unroll 4
    for (int ic = 0; ic < 64; ic++) {
        float xv = Xb[ic*HWSZ];
        unsigned long long x2 = pk2(xv, xv);
        const ulonglong2* w2 = reinterpret_cast<const ulonglong2*>(ws + (ic << 6));
#pragma unroll
        for (int o = 0; o < 16; o++) {
            ulonglong2 w = w2[o];
            acc[2*o]   = fma2(x2, w.x, acc[2*o]);
            acc[2*o+1] = fma2(x2, w.y, acc[2*o+1]);
        }
    }

    float* outb = g_comp + b*CC*HWSZ + p;
#pragma unroll
    for (int k = 0; k < 32; k++) {
        float2 f = up2(acc[k]);
        int oc = 2*k;
        outb[oc*HWSZ]       = fmaxf(f.x*sc[oc]   + bs[oc],   0.f);
        outb[(oc+1)*HWSZ]   = fmaxf(f.y*sc[oc+1] + bs[oc+1], 0.f);
    }
}

// ============================================================================
// Kernel 2: encode = 3x3 conv (64->100, pad 1) + bias + BN
// 256 threads = 16x16 spatial tile; each thread computes 10 output channels.
// grid = (64 tiles, 10 oc-groups, 4 batches). All weights for the oc-group
// staged in smem as [ic][tap][12] (10 used), input tile 18x18 per ic.
// ============================================================================
__global__ __launch_bounds__(256) void encode_kernel(
    const float* __restrict__ Wenc, const float* __restrict__ encb,
    const float* __restrict__ gamma, const float* __restrict__ beta,
    const float* __restrict__ mean,  const float* __restrict__ var)
{
    __shared__ __align__(16) float ws[64*9*12];   // 27.6 KB
    __shared__ float tile[18*18];
    __shared__ float sc2[10], bs2[10];

    int tid = threadIdx.x;
    int tx = tid & 15, ty = tid >> 4;
    int tileid = blockIdx.x;       // 0..63
    int g = blockIdx.y;            // 0..9 (oc group of 10)
    int b = blockIdx.z;
    int tyb = (tileid >> 3) << 4;
    int txb = (tileid & 7) << 4;

    for (int t = tid; t < 64*9*10; t += 256) {
        int ic = t / 90;
        int r  = t - ic*90;
        int k  = r / 10;
        int o  = r - k*10;
        ws[(ic*9 + k)*12 + o] = Wenc[((g*10 + o)*64 + ic)*9 + k];
    }
    if (tid < 10) {
        int oc = g*10 + tid;
        float inv = gamma[oc] * rsqrtf(var[oc] + 1e-5f);
        sc2[tid] = inv;
        bs2[tid] = beta[oc] - mean[oc]*inv + encb[oc]*inv;
    }

    unsigned long long acc[5];
#pragma unroll
    for (int i = 0; i < 5; i++) acc[i] = 0ULL;

    const float* inb = g_comp + b*CC*HWSZ;
    for (int ic = 0; ic < 64; ic++) {
        __syncthreads();
        for (int t = tid; t < 324; t += 256) {
            int r  = t / 18, cc = t - r*18;
            int iy = tyb + r - 1, ix = txb + cc - 1;
            float v = 0.f;
            if ((unsigned)iy < 128u && (unsigned)ix < 128u)
                v = inb[ic*HWSZ + iy*128 + ix];
            tile[t] = v;
        }
        __syncthreads();

        float v[9];
#pragma unroll
        for (int dr = 0; dr < 3; dr++)
#pragma unroll
            for (int dc = 0; dc < 3; dc++)
                v[dr*3+dc] = tile[(ty+dr)*18 + tx + dc];

#pragma unroll
        for (int k = 0; k < 9; k++) {
            unsigned long long x2 = pk2(v[k], v[k]);
            const float* wb = ws + (ic*9 + k)*12;
            ulonglong2 wA = *reinterpret_cast<const ulonglong2*>(wb);
            ulonglong2 wB = *reinterpret_cast<const ulonglong2*>(wb + 4);
            unsigned long long wC = *reinterpret_cast<const unsigned long long*>(wb + 8);
            acc[0] = fma2(x2, wA.x, acc[0]);
            acc[1] = fma2(x2, wA.y, acc[1]);
            acc[2] = fma2(x2, wB.x, acc[2]);
            acc[3] = fma2(x2, wB.y, acc[3]);
            acc[4] = fma2(x2, wC,   acc[4]);
        }
    }

    int y = tyb + ty, x = txb + tx;
    float* outb = g_enc + (b*ENCC + g*10)*HWSZ + y*128 + x;
#pragma unroll
    for (int k = 0; k < 5; k++) {
        float2 f = up2(acc[k]);
        outb[(2*k)*HWSZ]   = f.x*sc2[2*k]   + bs2[2*k];
        outb[(2*k+1)*HWSZ] = f.y*sc2[2*k+1] + bs2[2*k+1];
    }
}

// ============================================================================
// Kernel 3: pixel-shuffle + softmax(25) + CARAFE 5x5 dilated-2 apply.
// One block per (batch, output row y): 256 threads = x. Each thread holds its
// 25 softmax weights (packed f32x2 splat). Channel-pair loop: the 5x132 X tile
// for two channels lives in smem as float2, 25 FFMA2 per pair per thread.
// out[b,c,y,x] = sum_{i,j} w[i*5+j] * X[b,c,(y-4+2i)>>1,(x-4+2j)>>1] (0 if OOB)
// ============================================================================
__global__ __launch_bounds__(256) void carafe_kernel(
    const float* __restrict__ X, float* __restrict__ out)
{
    __shared__ unsigned long long stile[5*132];
    int x = threadIdx.x;
    int y = blockIdx.x;
    int b = blockIdx.y;

    // pixel shuffle: channel = k*4 + (y&1)*2 + (x&1), spatial (y>>1, x>>1)
    int sub = ((y & 1) << 1) | (x & 1);
    const float* encp = g_enc + (b*ENCC + sub)*HWSZ + (y >> 1)*128 + (x >> 1);

    float lg[25];
    float mx = -1e30f;
#pragma unroll
    for (int k = 0; k < 25; k++) {
        lg[k] = encp[(k*4)*HWSZ];
        mx = fmaxf(mx, lg[k]);
    }
    float s = 0.f;
#pragma unroll
    for (int k = 0; k < 25; k++) { lg[k] = __expf(lg[k] - mx); s += lg[k]; }
    float inv = 1.f / s;
    unsigned long long w2[25];
#pragma unroll
    for (int k = 0; k < 25; k++) { float wv = lg[k]*inv; w2[k] = pk2(wv, wv); }

    int q0 = (y - 4) >> 1;            // arithmetic shift = floor
    int p2 = ((x - 4) >> 1) + 2;      // tile col base (cols stored at +2)
    const float* Xb = X + b*CC*HWSZ;
    float* ob = out + b*CC*(HO*WO) + y*WO + x;

    for (int c = 0; c < 64; c += 2) {
        __syncthreads();
        const float* X0 = Xb + c*HWSZ;
        for (int t = threadIdx.x; t < 5*132; t += 256) {
            int i  = t / 132;
            int cc = t - i*132 - 2;
            int r  = q0 + i;
            float vx = 0.f, vy = 0.f;
            if ((unsigned)r < 128u && (unsigned)cc < 128u) {
                int off = r*128 + cc;
                vx = X0[off];
                vy = X0[HWSZ + off];
            }
            stile[t] = pk2(vx, vy);
        }
        __syncthreads();

        unsigned long long a0 = 0ULL, a1 = 0ULL;
#pragma unroll
        for (int i = 0; i < 5; i++) {
            int base = i*132 + p2;
#pragma unroll
            for (int j = 0; j < 5; j++) {
                int k = i*5 + j;
                if (k & 1) a1 = fma2(w2[k], stile[base + j], a1);
                else       a0 = fma2(w2[k], stile[base + j], a0);
            }
        }
        float2 f = up2(fma2(pk2(1.f,1.f), a0, a1));
        ob[c*(HO*WO)]     = f.x;
        ob[(c+1)*(HO*WO)] = f.y;
    }
}

// ============================================================================
extern "C" void kernel_launch(void* const* d_in, const int* in_sizes, int n_in,
                              void* d_out, int out_size)
{
    const float* X          = (const float*)d_in[0];
    const float* comp_w     = (const float*)d_in[1];
    const float* comp_gamma = (const float*)d_in[2];
    const float* comp_beta  = (const float*)d_in[3];
    const float* comp_mean  = (const float*)d_in[4];
    const float* comp_var   = (const float*)d_in[5];
    const float* enc_w      = (const float*)d_in[6];
    const float* enc_b      = (const float*)d_in[7];
    const float* enc_gamma  = (const float*)d_in[8];
    const float* enc_beta   = (const float*)d_in[9];
    const float* enc_mean   = (const float*)d_in[10];
    const float* enc_var    = (const float*)d_in[11];
    float* out = (float*)d_out;

    compress_kernel<<<BB*128, 128>>>(X, comp_w, comp_gamma, comp_beta,
                                     comp_mean, comp_var);
    encode_kernel<<<dim3(64, 10, BB), 256>>>(enc_w, enc_b, enc_gamma, enc_beta,
                                             enc_mean, enc_var);
    carafe_kernel<<<dim3(HO, BB), 256>>>(X, out);
}

// round 3
// speedup vs baseline: 1.0867x; 1.0867x over previous
#include <cuda_runtime.h>

#define BB 4
#define CC 64
#define HH 128
#define WW 128
#define HWSZ 16384
#define ENCC 100
#define HO 256
#define WO 256

typedef unsigned long long u64;

// scratch (static device arrays: allocation-free)
__device__ float g_comp[BB*CC*HWSZ];    // compressed features [4,64,128,128]
__device__ float g_enc[BB*ENCC*HWSZ];   // encoded logits (post-BN) [4,100,128,128]

// ---- packed f32x2 helpers (Blackwell FFMA2 path) ----
__device__ __forceinline__ u64 pk2(float lo, float hi) {
    u64 r;
    asm("mov.b64 %0, {%1, %2};" : "=l"(r) : "f"(lo), "f"(hi));
    return r;
}
__device__ __forceinline__ u64 fma2(u64 a, u64 b, u64 c) {
    u64 d;
    asm("fma.rn.f32x2 %0, %1, %2, %3;" : "=l"(d) : "l"(a), "l"(b), "l"(c));
    return d;
}
__device__ __forceinline__ float2 up2(u64 v) {
    float2 f;
    asm("mov.b64 {%0, %1}, %2;" : "=f"(f.x), "=f"(f.y) : "l"(v));
    return f;
}

// ============================================================================
// Kernel 1: compress = 1x1 conv (64->64) + BN + ReLU
// 256 threads, 1 pixel/thread, 32 oc/thread (blockIdx.y = oc half).
// Weights in smem with XOR-4 swizzle: coalesced LDG, ~4-way STS, LDS.128 reads.
// ============================================================================
__global__ __launch_bounds__(256) void compress_kernel(
    const float* __restrict__ X, const float* __restrict__ Wc,
    const float* __restrict__ gamma, const float* __restrict__ beta,
    const float* __restrict__ mean,  const float* __restrict__ var)
{
    __shared__ __align__(16) float ws[64*32];   // [ic][oc ^ ((ic&7)<<2)]
    __shared__ float sc[32], bs[32];
    int tid  = threadIdx.x;
    int half = blockIdx.y;          // 0/1 -> oc 0..31 / 32..63

    for (int t = tid; t < 2048; t += 256) {
        int oc = t >> 6, ic = t & 63;               // coalesced over ic
        ws[ic*32 + (oc ^ ((ic & 7) << 2))] = Wc[(half*32 + oc)*64 + ic];
    }
    if (tid < 32) {
        int oc = half*32 + tid;
        float inv = gamma[oc] * rsqrtf(var[oc] + 1e-5f);
        sc[tid] = inv;
        bs[tid] = beta[oc] - mean[oc]*inv;
    }
    __syncthreads();

    int b = blockIdx.z;
    int p = (blockIdx.x << 8) + tid;
    const float* Xb = X + b*CC*HWSZ + p;

    u64 acc[16];
#pragma unroll
    for (int i = 0; i < 16; i++) acc[i] = 0ULL;

#pragma unroll 4
    for (int ic = 0; ic < 64; ic++) {
        float xv = Xb[ic*HWSZ];
        u64 x2 = pk2(xv, xv);
        int s = ic & 7;
        const ulonglong2* w2 = reinterpret_cast<const ulonglong2*>(ws + (ic << 5));
#pragma unroll
        for (int m = 0; m < 8; m++) {
            ulonglong2 w = w2[m ^ s];      // group m (oc 4m..4m+3)
            acc[2*m]   = fma2(x2, w.x, acc[2*m]);
            acc[2*m+1] = fma2(x2, w.y, acc[2*m+1]);
        }
    }

    float* outb = g_comp + b*CC*HWSZ + half*32*HWSZ + p;
#pragma unroll
    for (int k = 0; k < 16; k++) {
        float2 f = up2(acc[k]);
        int oc = 2*k;
        outb[oc*HWSZ]     = fmaxf(f.x*sc[oc]   + bs[oc],   0.f);
        outb[(oc+1)*HWSZ] = fmaxf(f.y*sc[oc+1] + bs[oc+1], 0.f);
    }
}

// ============================================================================
// Kernel 2: encode = 3x3 conv (64->100, pad 1) + bias + BN
// 256 threads (tx 0..31, ty 0..7). Each thread: 4 pixels (rows 2ty,2ty+1;
// cols tx, tx+32 within a 64x16 tile) x 10 oc -> weight smem reads amortized
// 4x. Double-buffered 18x66 input tile, ONE barrier per ic.
// grid = (16 tiles, 10 oc-groups, 4 batches).
// ============================================================================
__global__ __launch_bounds__(256, 2) void encode_kernel(
    const float* __restrict__ Wenc, const float* __restrict__ encb,
    const float* __restrict__ gamma, const float* __restrict__ beta,
    const float* __restrict__ mean,  const float* __restrict__ var)
{
    __shared__ __align__(16) float ws[64*9*12];     // 27.6 KB, [ic][tap][12]
    __shared__ __align__(16) float tile[2][18*68];  // 9.8 KB double buffer
    __shared__ float sc2[10], bs2[10];

    int tid = threadIdx.x;
    int tx = tid & 31, ty = tid >> 5;
    int tileid = blockIdx.x;        // 0..15
    int g = blockIdx.y;             // oc group
    int b = blockIdx.z;
    int txb = (tileid & 1) << 6;    // 0 or 64
    int tyb = (tileid >> 1) << 4;   // 0..112

    // stage weights: coalesced global reads (5760 contiguous floats per group)
    const float* Wg = Wenc + g*10*64*9;
    for (int t = tid; t < 5760; t += 256) {
        int o = t / 576;
        int r = t - o*576;
        int ic = r / 9;
        int k  = r - ic*9;
        ws[(ic*9 + k)*12 + o] = Wg[t];
    }
    if (tid < 10) {
        int oc = g*10 + tid;
        float inv = gamma[oc] * rsqrtf(var[oc] + 1e-5f);
        sc2[tid] = inv;
        bs2[tid] = beta[oc] - mean[oc]*inv + encb[oc]*inv;
    }

    const float* inb = g_comp + b*CC*HWSZ;

    // fill buffer 0 with ic=0
    {
        const float* src = inb;
        for (int t = tid; t < 18*68; t += 256) {
            int r = t / 68, c = t - r*68;
            int iy = tyb - 1 + r, ix = txb - 1 + c;
            float v = 0.f;
            if ((unsigned)iy < 128u && (unsigned)ix < 128u)
                v = src[iy*128 + ix];
            tile[0][t] = v;
        }
    }

    u64 acc[2][2][5];   // [row a][side][oc-pair]
#pragma unroll
    for (int a = 0; a < 2; a++)
#pragma unroll
        for (int s = 0; s < 2; s++)
#pragma unroll
            for (int m = 0; m < 5; m++) acc[a][s][m] = 0ULL;

    for (int ic = 0; ic < 64; ic++) {
        __syncthreads();

        // prefetch next ic into the other buffer (overlaps with compute)
        if (ic + 1 < 64) {
            const float* src = inb + (ic+1)*HWSZ;
            float* buf = tile[(ic+1) & 1];
            for (int t = tid; t < 18*68; t += 256) {
                int r = t / 68, c = t - r*68;
                int iy = tyb - 1 + r, ix = txb - 1 + c;
                float v = 0.f;
                if ((unsigned)iy < 128u && (unsigned)ix < 128u)
                    v = src[iy*128 + ix];
                buf[t] = v;
            }
        }

        const float* tb = tile[ic & 1];
        // load + splat the 4x(2 sides x 3) window values
        u64 vv[4][2][3];
#pragma unroll
        for (int r = 0; r < 4; r++) {
            int rowbase = (2*ty + r)*68 + tx;
#pragma unroll
            for (int s = 0; s < 2; s++)
#pragma unroll
                for (int c = 0; c < 3; c++) {
                    float v = tb[rowbase + 32*s + c];
                    vv[r][s][c] = pk2(v, v);
                }
        }

        const float* wb = ws + ic*108;
#pragma unroll
        for (int k = 0; k < 9; k++) {
            int kr = k / 3, kc = k - kr*3;
            ulonglong2 wA = *reinterpret_cast<const ulonglong2*>(wb + k*12);
            ulonglong2 wB = *reinterpret_cast<const ulonglong2*>(wb + k*12 + 4);
            u64        wC = *reinterpret_cast<const u64*>(wb + k*12 + 8);
#pragma unroll
            for (int a = 0; a < 2; a++)
#pragma unroll
                for (int s = 0; s < 2; s++) {
                    u64 xv = vv[a + kr][s][kc];
                    acc[a][s][0] = fma2(xv, wA.x, acc[a][s][0]);
                    acc[a][s][1] = fma2(xv, wA.y, acc[a][s][1]);
                    acc[a][s][2] = fma2(xv, wB.x, acc[a][s][2]);
                    acc[a][s][3] = fma2(xv, wB.y, acc[a][s][3]);
                    acc[a][s][4] = fma2(xv, wC,   acc[a][s][4]);
                }
        }
    }

    // epilogue: BN + store (fully coalesced: warp writes 32 consecutive x)
#pragma unroll
    for (int a = 0; a < 2; a++) {
        int y = tyb + 2*ty + a;
#pragma unroll
        for (int s = 0; s < 2; s++) {
            int x = txb + tx + 32*s;
            float* op = g_enc + (b*ENCC + g*10)*HWSZ + y*128 + x;
#pragma unroll
            for (int m = 0; m < 5; m++) {
                float2 f = up2(acc[a][s][m]);
                op[(2*m)*HWSZ]   = f.x*sc2[2*m]   + bs2[2*m];
                op[(2*m+1)*HWSZ] = f.y*sc2[2*m+1] + bs2[2*m+1];
            }
        }
    }
}

// ============================================================================
// Kernel 3: pixel-shuffle + softmax(25) + CARAFE 5x5 dilated-2 apply.
// One block per (batch, output row y): 256 threads = x. 25 softmax weights
// per thread in registers; 4 channels per smem stage (ulonglong2 tile),
// 25 LDS.128 + 50 fma2 per stage per thread. 16 stages instead of 32.
// ============================================================================
__global__ __launch_bounds__(256) void carafe_kernel(
    const float* __restrict__ X, float* __restrict__ out)
{
    __shared__ __align__(16) ulonglong2 stile[5*132];   // 10.6 KB
    int x = threadIdx.x;
    int y = blockIdx.x;
    int b = blockIdx.y;

    // pixel shuffle: channel = k*4 + (y&1)*2 + (x&1), spatial (y>>1, x>>1)
    int sub = ((y & 1) << 1) | (x & 1);
    const float* encp = g_enc + (b*ENCC + sub)*HWSZ + (y >> 1)*128 + (x >> 1);

    float lg[25];
    float mx = -1e30f;
#pragma unroll
    for (int k = 0; k < 25; k++) {
        lg[k] = encp[(k*4)*HWSZ];
        mx = fmaxf(mx, lg[k]);
    }
    float s = 0.f;
#pragma unroll
    for (int k = 0; k < 25; k++) { lg[k] = __expf(lg[k] - mx); s += lg[k]; }
    float inv = 1.f / s;
    u64 w2[25];
#pragma unroll
    for (int k = 0; k < 25; k++) { float wv = lg[k]*inv; w2[k] = pk2(wv, wv); }

    int q0 = (y - 4) >> 1;            // arithmetic shift = floor
    int p2 = ((x - 4) >> 1) + 2;      // tile col base (cols stored at +2)
    const float* Xb = X + b*CC*HWSZ;
    float* ob = out + b*CC*(HO*WO) + y*WO + x;

    for (int c = 0; c < 64; c += 4) {
        __syncthreads();
        const float* X0 = Xb + c*HWSZ;
        for (int t = threadIdx.x; t < 5*132; t += 256) {
            int i  = t / 132;
            int cc = t - i*132 - 2;
            int r  = q0 + i;
            float v0 = 0.f, v1 = 0.f, v2 = 0.f, v3 = 0.f;
            if ((unsigned)r < 128u && (unsigned)cc < 128u) {
                int off = r*128 + cc;
                v0 = X0[off];
                v1 = X0[HWSZ + off];
                v2 = X0[2*HWSZ + off];
                v3 = X0[3*HWSZ + off];
            }
            ulonglong2 pk;
            pk.x = pk2(v0, v1);
            pk.y = pk2(v2, v3);
            stile[t] = pk;
        }
        __syncthreads();

        u64 a0 = 0ULL, a1 = 0ULL, b0 = 0ULL, b1 = 0ULL;
#pragma unroll
        for (int i = 0; i < 5; i++) {
            int base = i*132 + p2;
#pragma unroll
            for (int j = 0; j < 5; j++) {
                int k = i*5 + j;
                ulonglong2 sv = stile[base + j];
                if (k & 1) { a1 = fma2(w2[k], sv.x, a1); b1 = fma2(w2[k], sv.y, b1); }
                else       { a0 = fma2(w2[k], sv.x, a0); b0 = fma2(w2[k], sv.y, b0); }
            }
        }
        u64 one2 = pk2(1.f, 1.f);
        float2 fa = up2(fma2(one2, a0, a1));
        float2 fb = up2(fma2(one2, b0, b1));
        ob[c*(HO*WO)]       = fa.x;
        ob[(c+1)*(HO*WO)]   = fa.y;
        ob[(c+2)*(HO*WO)]   = fb.x;
        ob[(c+3)*(HO*WO)]   = fb.y;
    }
}

// ============================================================================
extern "C" void kernel_launch(void* const* d_in, const int* in_sizes, int n_in,
                              void* d_out, int out_size)
{
    const float* X          = (const float*)d_in[0];
    const float* comp_w     = (const float*)d_in[1];
    const float* comp_gamma = (const float*)d_in[2];
    const float* comp_beta  = (const float*)d_in[3];
    const float* comp_mean  = (const float*)d_in[4];
    const float* comp_var   = (const float*)d_in[5];
    const float* enc_w      = (const float*)d_in[6];
    const float* enc_b      = (const float*)d_in[7];
    const float* enc_gamma  = (const float*)d_in[8];
    const float* enc_beta   = (const float*)d_in[9];
    const float* enc_mean   = (const float*)d_in[10];
    const float* enc_var    = (const float*)d_in[11];
    float* out = (float*)d_out;

    compress_kernel<<<dim3(64, 2, BB), 256>>>(X, comp_w, comp_gamma, comp_beta,
                                              comp_mean, comp_var);
    encode_kernel<<<dim3(16, 10, BB), 256>>>(enc_w, enc_b, enc_gamma, enc_beta,
                                             enc_mean, enc_var);
    carafe_kernel<<<dim3(HO, BB), 256>>>(X, out);
}

// round 4
// speedup vs baseline: 1.6681x; 1.5351x over previous
#include <cuda_runtime.h>

#define BB 4
#define CC 64
#define HH 128
#define WW 128
#define HWSZ 16384
#define ENCC 100
#define HO 256
#define WO 256

typedef unsigned long long u64;

// scratch (static device arrays: allocation-free)
__device__ float g_comp[BB*CC*HWSZ];    // compressed features [4,64,128,128]
__device__ float g_enc[BB*ENCC*HWSZ];   // encoded logits (post-BN) [4,100,128,128]

// ---- packed f32x2 helpers (Blackwell FFMA2 path) ----
__device__ __forceinline__ u64 pk2(float lo, float hi) {
    u64 r;
    asm("mov.b64 %0, {%1, %2};" : "=l"(r) : "f"(lo), "f"(hi));
    return r;
}
__device__ __forceinline__ u64 fma2(u64 a, u64 b, u64 c) {
    u64 d;
    asm("fma.rn.f32x2 %0, %1, %2, %3;" : "=l"(d) : "l"(a), "l"(b), "l"(c));
    return d;
}
__device__ __forceinline__ float2 up2(u64 v) {
    float2 f;
    asm("mov.b64 {%0, %1}, %2;" : "=f"(f.x), "=f"(f.y) : "l"(v));
    return f;
}

// ============================================================================
// Kernel 1: compress = 1x1 conv (64->64) + BN + ReLU
// 256 threads, 2 adjacent pixels/thread (LDG.64), 16 oc/thread.
// grid = (32 px-blocks, 4 oc-quarters, 4 batches) = 512 blocks.
// Per ic: 1 LDG.64 + 4 broadcast LDS.128 + 16 FFMA2  -> fma-pipe bound.
// ============================================================================
__global__ __launch_bounds__(256) void compress_kernel(
    const float* __restrict__ X, const float* __restrict__ Wc,
    const float* __restrict__ gamma, const float* __restrict__ beta,
    const float* __restrict__ mean,  const float* __restrict__ var)
{
    __shared__ __align__(16) float ws[64*16];   // [ic][oc]
    __shared__ float sc[16], bs[16];
    int tid = threadIdx.x;
    int q   = blockIdx.y;           // oc quarter

    for (int t = tid; t < 1024; t += 256) {
        int oc = t >> 6, ic = t & 63;
        ws[ic*16 + oc] = Wc[(q*16 + oc)*64 + ic];
    }
    if (tid < 16) {
        int oc = q*16 + tid;
        float inv = gamma[oc] * rsqrtf(var[oc] + 1e-5f);
        sc[tid] = inv;
        bs[tid] = beta[oc] - mean[oc]*inv;
    }
    __syncthreads();

    int b = blockIdx.z;
    int p = ((blockIdx.x << 8) + tid) << 1;       // even pixel index
    const float2* Xb = reinterpret_cast<const float2*>(X + b*CC*HWSZ + p);

    u64 acc0[8], acc1[8];
#pragma unroll
    for (int i = 0; i < 8; i++) { acc0[i] = 0ULL; acc1[i] = 0ULL; }

#pragma unroll 4
    for (int ic = 0; ic < 64; ic++) {
        float2 xv = Xb[ic*(HWSZ/2)];
        u64 xa = pk2(xv.x, xv.x);
        u64 xc = pk2(xv.y, xv.y);
        const ulonglong2* w2 = reinterpret_cast<const ulonglong2*>(ws + (ic << 4));
#pragma unroll
        for (int m = 0; m < 4; m++) {
            ulonglong2 w = w2[m];                 // broadcast
            acc0[2*m]   = fma2(xa, w.x, acc0[2*m]);
            acc0[2*m+1] = fma2(xa, w.y, acc0[2*m+1]);
            acc1[2*m]   = fma2(xc, w.x, acc1[2*m]);
            acc1[2*m+1] = fma2(xc, w.y, acc1[2*m+1]);
        }
    }

    float* outb = g_comp + b*CC*HWSZ + q*16*HWSZ + p;
#pragma unroll
    for (int k = 0; k < 8; k++) {
        float2 f0 = up2(acc0[k]);   // pixel p,   oc pair
        float2 f1 = up2(acc1[k]);   // pixel p+1, oc pair
        int oc = 2*k;
        float2 o0 = make_float2(fmaxf(f0.x*sc[oc] + bs[oc], 0.f),
                                fmaxf(f1.x*sc[oc] + bs[oc], 0.f));
        float2 o1 = make_float2(fmaxf(f0.y*sc[oc+1] + bs[oc+1], 0.f),
                                fmaxf(f1.y*sc[oc+1] + bs[oc+1], 0.f));
        *reinterpret_cast<float2*>(outb + oc*HWSZ)     = o0;
        *reinterpret_cast<float2*>(outb + (oc+1)*HWSZ) = o1;
    }
}

// ============================================================================
// Kernel 2: encode = 3x3 conv (64->100, pad 1) + bias + BN
// 256 threads (tx 0..31, ty 0..7). 4 px/thread x 10 oc.
// Register-pipelined input tile: geometry precomputed once; LDG for ic+1
// issued BEFORE the 180-fma2 compute, STS after -> no exposed LDG latency.
// Double-buffered 18x68 tile, ONE barrier per ic.
// ============================================================================
__global__ __launch_bounds__(256, 2) void encode_kernel(
    const float* __restrict__ Wenc, const float* __restrict__ encb,
    const float* __restrict__ gamma, const float* __restrict__ beta,
    const float* __restrict__ mean,  const float* __restrict__ var)
{
    __shared__ __align__(16) float ws[64*9*12];     // 27.6 KB, [ic][tap][12]
    __shared__ __align__(16) float tile[2][18*68];  // 9.8 KB double buffer
    __shared__ float sc2[10], bs2[10];

    int tid = threadIdx.x;
    int tx = tid & 31, ty = tid >> 5;
    int tileid = blockIdx.x;        // 0..15
    int g = blockIdx.y;             // oc group
    int b = blockIdx.z;
    int txb = (tileid & 1) << 6;    // 0 or 64
    int tyb = (tileid >> 1) << 4;   // 0..112

    // stage weights: coalesced global reads (5760 contiguous floats per group)
    const float* Wg = Wenc + g*10*64*9;
    for (int t = tid; t < 5760; t += 256) {
        int o = t / 576;
        int r = t - o*576;
        int ic = r / 9;
        int k  = r - ic*9;
        ws[(ic*9 + k)*12 + o] = Wg[t];
    }
    if (tid < 10) {
        int oc = g*10 + tid;
        float inv = gamma[oc] * rsqrtf(var[oc] + 1e-5f);
        sc2[tid] = inv;
        bs2[tid] = beta[oc] - mean[oc]*inv + encb[oc]*inv;
    }

    // fill geometry (same for every ic)
    int  eoff[5];
    bool eval[5];
#pragma unroll
    for (int k = 0; k < 5; k++) {
        int t = tid + k*256;
        int r = t / 68, c = t - r*68;
        int iy = tyb - 1 + r, ix = txb - 1 + c;
        bool v = (t < 1224) && ((unsigned)iy < 128u) && ((unsigned)ix < 128u);
        eval[k] = v;
        eoff[k] = v ? iy*128 + ix : 0;
    }

    const float* inb = g_comp + b*CC*HWSZ;

    // prologue: ic=0 into buffer 0
    float rv[5];
#pragma unroll
    for (int k = 0; k < 5; k++) rv[k] = eval[k] ? inb[eoff[k]] : 0.f;
#pragma unroll
    for (int k = 0; k < 5; k++)
        if (tid + k*256 < 1224) tile[0][tid + k*256] = rv[k];
    __syncthreads();

    u64 acc[2][2][5];   // [row a][side][oc-pair]
#pragma unroll
    for (int a = 0; a < 2; a++)
#pragma unroll
        for (int s = 0; s < 2; s++)
#pragma unroll
            for (int m = 0; m < 5; m++) acc[a][s][m] = 0ULL;

    for (int ic = 0; ic < 64; ic++) {
        // issue next-ic loads FIRST (latency hidden by compute below)
        if (ic + 1 < 64) {
            const float* src = inb + (ic+1)*HWSZ;
#pragma unroll
            for (int k = 0; k < 5; k++) rv[k] = eval[k] ? src[eoff[k]] : 0.f;
        }

        const float* tb = tile[ic & 1];
        float vvf[4][2][3];
#pragma unroll
        for (int r = 0; r < 4; r++) {
            int rowbase = (2*ty + r)*68 + tx;
#pragma unroll
            for (int s = 0; s < 2; s++)
#pragma unroll
                for (int c = 0; c < 3; c++)
                    vvf[r][s][c] = tb[rowbase + 32*s + c];
        }

        const float* wb = ws + ic*108;
#pragma unroll
        for (int k = 0; k < 9; k++) {
            int kr = k / 3, kc = k - kr*3;
            ulonglong2 wA = *reinterpret_cast<const ulonglong2*>(wb + k*12);
            ulonglong2 wB = *reinterpret_cast<const ulonglong2*>(wb + k*12 + 4);
            u64        wC = *reinterpret_cast<const u64*>(wb + k*12 + 8);
#pragma unroll
            for (int a = 0; a < 2; a++)
#pragma unroll
                for (int s = 0; s < 2; s++) {
                    float v = vvf[a + kr][s][kc];
                    u64 xv = pk2(v, v);
                    acc[a][s][0] = fma2(xv, wA.x, acc[a][s][0]);
                    acc[a][s][1] = fma2(xv, wA.y, acc[a][s][1]);
                    acc[a][s][2] = fma2(xv, wB.x, acc[a][s][2]);
                    acc[a][s][3] = fma2(xv, wB.y, acc[a][s][3]);
                    acc[a][s][4] = fma2(xv, wC,   acc[a][s][4]);
                }
        }

        if (ic + 1 < 64) {
            float* buf = tile[(ic+1) & 1];
#pragma unroll
            for (int k = 0; k < 5; k++)
                if (tid + k*256 < 1224) buf[tid + k*256] = rv[k];
        }
        __syncthreads();
    }

    // epilogue: BN + store (fully coalesced: warp writes 32 consecutive x)
#pragma unroll
    for (int a = 0; a < 2; a++) {
        int y = tyb + 2*ty + a;
#pragma unroll
        for (int s = 0; s < 2; s++) {
            int x = txb + tx + 32*s;
            float* op = g_enc + (b*ENCC + g*10)*HWSZ + y*128 + x;
#pragma unroll
            for (int m = 0; m < 5; m++) {
                float2 f = up2(acc[a][s][m]);
                op[(2*m)*HWSZ]   = f.x*sc2[2*m]   + bs2[2*m];
                op[(2*m+1)*HWSZ] = f.y*sc2[2*m+1] + bs2[2*m+1];
            }
        }
    }
}

// ============================================================================
// Kernel 3: pixel-shuffle + softmax(25) + CARAFE 5x5 dilated-2 apply.
// One block per (batch, output row y). 25 softmax weights in registers.
// 4 channels per stage; register-pipelined channel fill with double-buffered
// smem tile -> one barrier per stage, no exposed LDG latency.
// ============================================================================
__global__ __launch_bounds__(256) void carafe_kernel(
    const float* __restrict__ X, float* __restrict__ out)
{
    __shared__ __align__(16) ulonglong2 stile[2][5*132];   // 21.1 KB
    int x = threadIdx.x;
    int y = blockIdx.x;
    int b = blockIdx.y;

    // pixel shuffle: channel = k*4 + (y&1)*2 + (x&1), spatial (y>>1, x>>1)
    int sub = ((y & 1) << 1) | (x & 1);
    const float* encp = g_enc + (b*ENCC + sub)*HWSZ + (y >> 1)*128 + (x >> 1);

    float lg[25];
    float mx = -1e30f;
#pragma unroll
    for (int k = 0; k < 25; k++) {
        lg[k] = encp[(k*4)*HWSZ];
        mx = fmaxf(mx, lg[k]);
    }
    float s = 0.f;
#pragma unroll
    for (int k = 0; k < 25; k++) { lg[k] = __expf(lg[k] - mx); s += lg[k]; }
    float inv = 1.f / s;
    u64 w2[25];
#pragma unroll
    for (int k = 0; k < 25; k++) { float wv = lg[k]*inv; w2[k] = pk2(wv, wv); }

    int q0 = (y - 4) >> 1;            // arithmetic shift = floor
    int p2 = ((x - 4) >> 1) + 2;      // tile col base (cols stored at +2)
    const float* Xb = X + b*CC*HWSZ;
    float* ob = out + b*CC*(HO*WO) + y*WO + x;

    // fill geometry (same rows for all channel stages)
    int  foff[3];
    bool fval[3];
#pragma unroll
    for (int k = 0; k < 3; k++) {
        int t = x + k*256;
        int i = t / 132;
        int cc = t - i*132 - 2;
        int r  = q0 + i;
        bool v = (t < 660) && ((unsigned)r < 128u) && ((unsigned)cc < 128u);
        fval[k] = v;
        foff[k] = v ? r*128 + cc : 0;
    }

    // prologue: channels 0..3 into buffer 0
    float rv[3][4];
#pragma unroll
    for (int k = 0; k < 3; k++) {
        const float* p = Xb + foff[k];
#pragma unroll
        for (int j = 0; j < 4; j++) rv[k][j] = fval[k] ? p[j*HWSZ] : 0.f;
    }
#pragma unroll
    for (int k = 0; k < 3; k++)
        if (x + k*256 < 660) {
            ulonglong2 pk;
            pk.x = pk2(rv[k][0], rv[k][1]);
            pk.y = pk2(rv[k][2], rv[k][3]);
            stile[0][x + k*256] = pk;
        }
    __syncthreads();

    u64 one2 = pk2(1.f, 1.f);
    for (int ci = 0; ci < 16; ci++) {
        int c = ci*4;
        // issue next-stage loads first
        if (ci + 1 < 16) {
#pragma unroll
            for (int k = 0; k < 3; k++) {
                const float* p = Xb + (c+4)*HWSZ + foff[k];
#pragma unroll
                for (int j = 0; j < 4; j++) rv[k][j] = fval[k] ? p[j*HWSZ] : 0.f;
            }
        }

        const ulonglong2* tb = stile[ci & 1];
        u64 a0 = 0ULL, a1 = 0ULL, b0 = 0ULL, b1 = 0ULL;
#pragma unroll
        for (int i = 0; i < 5; i++) {
            int base = i*132 + p2;
#pragma unroll
            for (int j = 0; j < 5; j++) {
                int k = i*5 + j;
                ulonglong2 sv = tb[base + j];
                if (k & 1) { a1 = fma2(w2[k], sv.x, a1); b1 = fma2(w2[k], sv.y, b1); }
                else       { a0 = fma2(w2[k], sv.x, a0); b0 = fma2(w2[k], sv.y, b0); }
            }
        }
        float2 fa = up2(fma2(one2, a0, a1));
        float2 fb = up2(fma2(one2, b0, b1));
        ob[c*(HO*WO)]       = fa.x;
        ob[(c+1)*(HO*WO)]   = fa.y;
        ob[(c+2)*(HO*WO)]   = fb.x;
        ob[(c+3)*(HO*WO)]   = fb.y;

        if (ci + 1 < 16) {
            ulonglong2* buf = stile[(ci+1) & 1];
#pragma unroll
            for (int k = 0; k < 3; k++)
                if (x + k*256 < 660) {
                    ulonglong2 pk;
                    pk.x = pk2(rv[k][0], rv[k][1]);
                    pk.y = pk2(rv[k][2], rv[k][3]);
                    buf[x + k*256] = pk;
                }
        }
        __syncthreads();
    }
}

// ============================================================================
extern "C" void kernel_launch(void* const* d_in, const int* in_sizes, int n_in,
                              void* d_out, int out_size)
{
    const float* X          = (const float*)d_in[0];
    const float* comp_w     = (const float*)d_in[1];
    const float* comp_gamma = (const float*)d_in[2];
    const float* comp_beta  = (const float*)d_in[3];
    const float* comp_mean  = (const float*)d_in[4];
    const float* comp_var   = (const float*)d_in[5];
    const float* enc_w      = (const float*)d_in[6];
    const float* enc_b      = (const float*)d_in[7];
    const float* enc_gamma  = (const float*)d_in[8];
    const float* enc_beta   = (const float*)d_in[9];
    const float* enc_mean   = (const float*)d_in[10];
    const float* enc_var    = (const float*)d_in[11];
    float* out = (float*)d_out;

    compress_kernel<<<dim3(32, 4, BB), 256>>>(X, comp_w, comp_gamma, comp_beta,
                                              comp_mean, comp_var);
    encode_kernel<<<dim3(16, 10, BB), 256>>>(enc_w, enc_b, enc_gamma, enc_beta,
                                             enc_mean, enc_var);
    carafe_kernel<<<dim3(HO, BB), 256>>>(X, out);
}

// round 5
// speedup vs baseline: 1.6982x; 1.0180x over previous
#include <cuda_runtime.h>

#define BB 4
#define CC 64
#define HH 128
#define WW 128
#define HWSZ 16384
#define ENCC 100
#define HO 256
#define WO 256

typedef unsigned long long u64;

// scratch (static device arrays: allocation-free)
__device__ float g_comp[BB*CC*HWSZ];    // compressed features [4,64,128,128]
__device__ float g_enc[BB*ENCC*HWSZ];   // encoded logits (post-BN) [4,100,128,128]

// ---- packed f32x2 helpers (Blackwell FFMA2 path) ----
__device__ __forceinline__ u64 pk2(float lo, float hi) {
    u64 r;
    asm("mov.b64 %0, {%1, %2};" : "=l"(r) : "f"(lo), "f"(hi));
    return r;
}
__device__ __forceinline__ u64 fma2(u64 a, u64 b, u64 c) {
    u64 d;
    asm("fma.rn.f32x2 %0, %1, %2, %3;" : "=l"(d) : "l"(a), "l"(b), "l"(c));
    return d;
}
__device__ __forceinline__ float2 up2(u64 v) {
    float2 f;
    asm("mov.b64 {%0, %1}, %2;" : "=f"(f.x), "=f"(f.y) : "l"(v));
    return f;
}

// ============================================================================
// Kernel 1: compress = 1x1 conv (64->64) + BN + ReLU
// 256 threads, 2 adjacent pixels/thread (LDG.64), 16 oc/thread.
// ic loop unrolled x8 -> 8 LDG.64 in flight (hides L2 latency).
// grid = (32 px-blocks, 4 oc-quarters, 4 batches) = 512 blocks.
// ============================================================================
__global__ __launch_bounds__(256) void compress_kernel(
    const float* __restrict__ X, const float* __restrict__ Wc,
    const float* __restrict__ gamma, const float* __restrict__ beta,
    const float* __restrict__ mean,  const float* __restrict__ var)
{
    __shared__ __align__(16) float ws[64*16];   // [ic][oc]
    __shared__ float sc[16], bs[16];
    int tid = threadIdx.x;
    int q   = blockIdx.y;           // oc quarter

    for (int t = tid; t < 1024; t += 256) {
        int oc = t >> 6, ic = t & 63;
        ws[ic*16 + oc] = Wc[(q*16 + oc)*64 + ic];
    }
    if (tid < 16) {
        int oc = q*16 + tid;
        float inv = gamma[oc] * rsqrtf(var[oc] + 1e-5f);
        sc[tid] = inv;
        bs[tid] = beta[oc] - mean[oc]*inv;
    }
    __syncthreads();

    int b = blockIdx.z;
    int p = ((blockIdx.x << 8) + tid) << 1;       // even pixel index
    const float2* Xb = reinterpret_cast<const float2*>(X + b*CC*HWSZ + p);

    u64 acc0[8], acc1[8];
#pragma unroll
    for (int i = 0; i < 8; i++) { acc0[i] = 0ULL; acc1[i] = 0ULL; }

    for (int ic0 = 0; ic0 < 64; ic0 += 8) {
        // batch 8 independent loads first (MLP=8)
        float2 xv[8];
#pragma unroll
        for (int u = 0; u < 8; u++) xv[u] = Xb[(ic0 + u)*(HWSZ/2)];
#pragma unroll
        for (int u = 0; u < 8; u++) {
            int ic = ic0 + u;
            u64 xa = pk2(xv[u].x, xv[u].x);
            u64 xc = pk2(xv[u].y, xv[u].y);
            const ulonglong2* w2 = reinterpret_cast<const ulonglong2*>(ws + (ic << 4));
#pragma unroll
            for (int m = 0; m < 4; m++) {
                ulonglong2 w = w2[m];                 // broadcast
                acc0[2*m]   = fma2(xa, w.x, acc0[2*m]);
                acc0[2*m+1] = fma2(xa, w.y, acc0[2*m+1]);
                acc1[2*m]   = fma2(xc, w.x, acc1[2*m]);
                acc1[2*m+1] = fma2(xc, w.y, acc1[2*m+1]);
            }
        }
    }

    float* outb = g_comp + b*CC*HWSZ + q*16*HWSZ + p;
#pragma unroll
    for (int k = 0; k < 8; k++) {
        float2 f0 = up2(acc0[k]);   // pixel p,   oc pair
        float2 f1 = up2(acc1[k]);   // pixel p+1, oc pair
        int oc = 2*k;
        float2 o0 = make_float2(fmaxf(f0.x*sc[oc] + bs[oc], 0.f),
                                fmaxf(f1.x*sc[oc] + bs[oc], 0.f));
        float2 o1 = make_float2(fmaxf(f0.y*sc[oc+1] + bs[oc+1], 0.f),
                                fmaxf(f1.y*sc[oc+1] + bs[oc+1], 0.f));
        *reinterpret_cast<float2*>(outb + oc*HWSZ)     = o0;
        *reinterpret_cast<float2*>(outb + (oc+1)*HWSZ) = o1;
    }
}

// ============================================================================
// Kernel 2: encode = 3x3 conv (64->100, pad 1) + bias + BN
// 256 threads (tx 0..31, ty 0..7). 4 px/thread x 10 oc.
// Register-pipelined input tile (LDG for ic+1 before compute), double-buffered
// 18x68 tile, one barrier per ic.
// ============================================================================
__global__ __launch_bounds__(256, 2) void encode_kernel(
    const float* __restrict__ Wenc, const float* __restrict__ encb,
    const float* __restrict__ gamma, const float* __restrict__ beta,
    const float* __restrict__ mean,  const float* __restrict__ var)
{
    __shared__ __align__(16) float ws[64*9*12];     // 27.6 KB, [ic][tap][12]
    __shared__ __align__(16) float tile[2][18*68];  // 9.8 KB double buffer
    __shared__ float sc2[10], bs2[10];

    int tid = threadIdx.x;
    int tx = tid & 31, ty = tid >> 5;
    int tileid = blockIdx.x;        // 0..15
    int g = blockIdx.y;             // oc group
    int b = blockIdx.z;
    int txb = (tileid & 1) << 6;    // 0 or 64
    int tyb = (tileid >> 1) << 4;   // 0..112

    const float* Wg = Wenc + g*10*64*9;
    for (int t = tid; t < 5760; t += 256) {
        int o = t / 576;
        int r = t - o*576;
        int ic = r / 9;
        int k  = r - ic*9;
        ws[(ic*9 + k)*12 + o] = Wg[t];
    }
    if (tid < 10) {
        int oc = g*10 + tid;
        float inv = gamma[oc] * rsqrtf(var[oc] + 1e-5f);
        sc2[tid] = inv;
        bs2[tid] = beta[oc] - mean[oc]*inv + encb[oc]*inv;
    }

    int  eoff[5];
    bool eval[5];
#pragma unroll
    for (int k = 0; k < 5; k++) {
        int t = tid + k*256;
        int r = t / 68, c = t - r*68;
        int iy = tyb - 1 + r, ix = txb - 1 + c;
        bool v = (t < 1224) && ((unsigned)iy < 128u) && ((unsigned)ix < 128u);
        eval[k] = v;
        eoff[k] = v ? iy*128 + ix : 0;
    }

    const float* inb = g_comp + b*CC*HWSZ;

    float rv[5];
#pragma unroll
    for (int k = 0; k < 5; k++) rv[k] = eval[k] ? inb[eoff[k]] : 0.f;
#pragma unroll
    for (int k = 0; k < 5; k++)
        if (tid + k*256 < 1224) tile[0][tid + k*256] = rv[k];
    __syncthreads();

    u64 acc[2][2][5];   // [row a][side][oc-pair]
#pragma unroll
    for (int a = 0; a < 2; a++)
#pragma unroll
        for (int s = 0; s < 2; s++)
#pragma unroll
            for (int m = 0; m < 5; m++) acc[a][s][m] = 0ULL;

    for (int ic = 0; ic < 64; ic++) {
        if (ic + 1 < 64) {
            const float* src = inb + (ic+1)*HWSZ;
#pragma unroll
            for (int k = 0; k < 5; k++) rv[k] = eval[k] ? src[eoff[k]] : 0.f;
        }

        const float* tb = tile[ic & 1];
        float vvf[4][2][3];
#pragma unroll
        for (int r = 0; r < 4; r++) {
            int rowbase = (2*ty + r)*68 + tx;
#pragma unroll
            for (int s = 0; s < 2; s++)
#pragma unroll
                for (int c = 0; c < 3; c++)
                    vvf[r][s][c] = tb[rowbase + 32*s + c];
        }

        const float* wb = ws + ic*108;
#pragma unroll
        for (int k = 0; k < 9; k++) {
            int kr = k / 3, kc = k - kr*3;
            ulonglong2 wA = *reinterpret_cast<const ulonglong2*>(wb + k*12);
            ulonglong2 wB = *reinterpret_cast<const ulonglong2*>(wb + k*12 + 4);
            u64        wC = *reinterpret_cast<const u64*>(wb + k*12 + 8);
#pragma unroll
            for (int a = 0; a < 2; a++)
#pragma unroll
                for (int s = 0; s < 2; s++) {
                    float v = vvf[a + kr][s][kc];
                    u64 xv = pk2(v, v);
                    acc[a][s][0] = fma2(xv, wA.x, acc[a][s][0]);
                    acc[a][s][1] = fma2(xv, wA.y, acc[a][s][1]);
                    acc[a][s][2] = fma2(xv, wB.x, acc[a][s][2]);
                    acc[a][s][3] = fma2(xv, wB.y, acc[a][s][3]);
                    acc[a][s][4] = fma2(xv, wC,   acc[a][s][4]);
                }
        }

        if (ic + 1 < 64) {
            float* buf = tile[(ic+1) & 1];
#pragma unroll
            for (int k = 0; k < 5; k++)
                if (tid + k*256 < 1224) buf[tid + k*256] = rv[k];
        }
        __syncthreads();
    }

#pragma unroll
    for (int a = 0; a < 2; a++) {
        int y = tyb + 2*ty + a;
#pragma unroll
        for (int s = 0; s < 2; s++) {
            int x = txb + tx + 32*s;
            float* op = g_enc + (b*ENCC + g*10)*HWSZ + y*128 + x;
#pragma unroll
            for (int m = 0; m < 5; m++) {
                float2 f = up2(acc[a][s][m]);
                op[(2*m)*HWSZ]   = f.x*sc2[2*m]   + bs2[2*m];
                op[(2*m+1)*HWSZ] = f.y*sc2[2*m+1] + bs2[2*m+1];
            }
        }
    }
}

// ============================================================================
// Kernel 3: pixel-shuffle + softmax(25) + CARAFE apply.
// KEY: output rows 2Y and 2Y+1 (and col pairs) share the SAME 25 input taps —
// only softmax weights differ. One block per (b, low-res row Y): each thread
// computes out rows 2Y and 2Y+1 at column x, holding TWO 25-weight sets.
// Per 4-channel stage: 25 LDS.128 reused for both rows -> 100 fma2 per 25 LDS.
// Fills/barriers halved vs row-per-block. Register-pipelined channel fill.
// ============================================================================
__global__ __launch_bounds__(256) void carafe_kernel(
    const float* __restrict__ X, float* __restrict__ out)
{
    __shared__ __align__(16) ulonglong2 stile[2][5*132];   // 21.1 KB
    int x = threadIdx.x;
    int Y = blockIdx.x;            // low-res row 0..127
    int b = blockIdx.y;
    int y0 = 2*Y;                  // output rows y0, y0+1

    // weights: sub for (y0,x) = (x&1); for (y0+1,x) = 2+(x&1)
    const float* encp = g_enc + b*ENCC*HWSZ + Y*128 + (x >> 1);
    int sub0 = (x & 1);

    float w0[25], w1[25];
    {
        float lg[25];
        float mx = -1e30f;
#pragma unroll
        for (int k = 0; k < 25; k++) {
            lg[k] = encp[(k*4 + sub0)*HWSZ];
            mx = fmaxf(mx, lg[k]);
        }
        float s = 0.f;
#pragma unroll
        for (int k = 0; k < 25; k++) { lg[k] = __expf(lg[k] - mx); s += lg[k]; }
        float inv = 1.f / s;
#pragma unroll
        for (int k = 0; k < 25; k++) w0[k] = lg[k]*inv;
    }
    {
        float lg[25];
        float mx = -1e30f;
#pragma unroll
        for (int k = 0; k < 25; k++) {
            lg[k] = encp[(k*4 + sub0 + 2)*HWSZ];
            mx = fmaxf(mx, lg[k]);
        }
        float s = 0.f;
#pragma unroll
        for (int k = 0; k < 25; k++) { lg[k] = __expf(lg[k] - mx); s += lg[k]; }
        float inv = 1.f / s;
#pragma unroll
        for (int k = 0; k < 25; k++) w1[k] = lg[k]*inv;
    }

    int q0 = Y - 2;                   // same tap rows for y0 and y0+1
    int p2 = ((x - 4) >> 1) + 2;      // tile col base (cols stored at +2)
    const float* Xb = X + b*CC*HWSZ;
    float* ob0 = out + b*CC*(HO*WO) + y0*WO + x;
    float* ob1 = ob0 + WO;

    // fill geometry (rows q0..q0+4, same for all channel stages)
    int  foff[3];
    bool fval[3];
#pragma unroll
    for (int k = 0; k < 3; k++) {
        int t = x + k*256;
        int i = t / 132;
        int cc = t - i*132 - 2;
        int r  = q0 + i;
        bool v = (t < 660) && ((unsigned)r < 128u) && ((unsigned)cc < 128u);
        fval[k] = v;
        foff[k] = v ? r*128 + cc : 0;
    }

    // prologue: channels 0..3 into buffer 0
    float rv[3][4];
#pragma unroll
    for (int k = 0; k < 3; k++) {
        const float* p = Xb + foff[k];
#pragma unroll
        for (int j = 0; j < 4; j++) rv[k][j] = fval[k] ? p[j*HWSZ] : 0.f;
    }
#pragma unroll
    for (int k = 0; k < 3; k++)
        if (x + k*256 < 660) {
            ulonglong2 pk;
            pk.x = pk2(rv[k][0], rv[k][1]);
            pk.y = pk2(rv[k][2], rv[k][3]);
            stile[0][x + k*256] = pk;
        }
    __syncthreads();

    for (int ci = 0; ci < 16; ci++) {
        int c = ci*4;
        // issue next-stage loads first (latency hidden by compute)
        if (ci + 1 < 16) {
#pragma unroll
            for (int k = 0; k < 3; k++) {
                const float* p = Xb + (c+4)*HWSZ + foff[k];
#pragma unroll
                for (int j = 0; j < 4; j++) rv[k][j] = fval[k] ? p[j*HWSZ] : 0.f;
            }
        }

        const ulonglong2* tb = stile[ci & 1];
        u64 r0a = 0ULL, r0b = 0ULL;   // row y0, ch pairs (c,c+1),(c+2,c+3)
        u64 r1a = 0ULL, r1b = 0ULL;   // row y0+1
#pragma unroll
        for (int i = 0; i < 5; i++) {
            int base = i*132 + p2;
#pragma unroll
            for (int j = 0; j < 5; j++) {
                int k = i*5 + j;
                ulonglong2 sv = tb[base + j];
                u64 ww0 = pk2(w0[k], w0[k]);
                u64 ww1 = pk2(w1[k], w1[k]);
                r0a = fma2(ww0, sv.x, r0a);
                r0b = fma2(ww0, sv.y, r0b);
                r1a = fma2(ww1, sv.x, r1a);
                r1b = fma2(ww1, sv.y, r1b);
            }
        }
        float2 f0a = up2(r0a), f0b = up2(r0b);
        float2 f1a = up2(r1a), f1b = up2(r1b);
        ob0[c*(HO*WO)]     = f0a.x;
        ob0[(c+1)*(HO*WO)] = f0a.y;
        ob0[(c+2)*(HO*WO)] = f0b.x;
        ob0[(c+3)*(HO*WO)] = f0b.y;
        ob1[c*(HO*WO)]     = f1a.x;
        ob1[(c+1)*(HO*WO)] = f1a.y;
        ob1[(c+2)*(HO*WO)] = f1b.x;
        ob1[(c+3)*(HO*WO)] = f1b.y;

        if (ci + 1 < 16) {
            ulonglong2* buf = stile[(ci+1) & 1];
#pragma unroll
            for (int k = 0; k < 3; k++)
                if (x + k*256 < 660) {
                    ulonglong2 pk;
                    pk.x = pk2(rv[k][0], rv[k][1]);
                    pk.y = pk2(rv[k][2], rv[k][3]);
                    buf[x + k*256] = pk;
                }
        }
        __syncthreads();
    }
}

// ============================================================================
extern "C" void kernel_launch(void* const* d_in, const int* in_sizes, int n_in,
                              void* d_out, int out_size)
{
    const float* X          = (const float*)d_in[0];
    const float* comp_w     = (const float*)d_in[1];
    const float* comp_gamma = (const float*)d_in[2];
    const float* comp_beta  = (const float*)d_in[3];
    const float* comp_mean  = (const float*)d_in[4];
    const float* comp_var   = (const float*)d_in[5];
    const float* enc_w      = (const float*)d_in[6];
    const float* enc_b      = (const float*)d_in[7];
    const float* enc_gamma  = (const float*)d_in[8];
    const float* enc_beta   = (const float*)d_in[9];
    const float* enc_mean   = (const float*)d_in[10];
    const float* enc_var    = (const float*)d_in[11];
    float* out = (float*)d_out;

    compress_kernel<<<dim3(32, 4, BB), 256>>>(X, comp_w, comp_gamma, comp_beta,
                                              comp_mean, comp_var);
    encode_kernel<<<dim3(16, 10, BB), 256>>>(enc_w, enc_b, enc_gamma, enc_beta,
                                             enc_mean, enc_var);
    carafe_kernel<<<dim3(HH, BB), 256>>>(X, out);
}

// round 11
// speedup vs baseline: 2.7848x; 1.6399x over previous
#include <cuda_runtime.h>
#include <cuda_bf16.h>

#define BB 4
#define CC 64
#define HH 128
#define WW 128
#define HWSZ 16384
#define HO 256
#define WO 256
#define ECP 128          // padded channel-last stride for g_enc2

typedef unsigned long long u64;
typedef unsigned int u32;

// ---------------- scratch (static device arrays: allocation-free) ----------
// compressed features, NHWC bf16 hi/lo: ((b*HWSZ + pixel)*64 + ch)
__device__ __nv_bfloat16 g_chi[BB*HWSZ*64];
__device__ __nv_bfloat16 g_clo[BB*HWSZ*64];
// encode weights, per tap [128 oc x 64 ic] bf16, PRE-SWIZZLED (SW128), scaled by BN inv
__device__ __nv_bfloat16 g_whi[9*128*64];
__device__ __nv_bfloat16 g_wlo[9*128*64];
__device__ float g_shift[128];
// encoded logits, channel-last: [b][Y][x][128]
__device__ float g_enc2[BB*HH*WW*ECP];

// ---- packed f32x2 helpers ----
__device__ __forceinline__ u64 pk2(float lo, float hi) {
    u64 r; asm("mov.b64 %0, {%1, %2};" : "=l"(r) : "f"(lo), "f"(hi)); return r;
}
__device__ __forceinline__ u64 fma2(u64 a, u64 b, u64 c) {
    u64 d; asm("fma.rn.f32x2 %0, %1, %2, %3;" : "=l"(d) : "l"(a), "l"(b), "l"(c)); return d;
}
__device__ __forceinline__ float2 up2(u64 v) {
    float2 f; asm("mov.b64 {%0, %1}, %2;" : "=f"(f.x), "=f"(f.y) : "l"(v)); return f;
}
__device__ __forceinline__ u32 smem_u32(const void* p) {
    u32 a; asm("{ .reg .u64 t; cvta.to.shared.u64 t, %1; cvt.u32.u64 %0, t; }" : "=r"(a) : "l"(p));
    return a;
}
__device__ __forceinline__ u32 pack_bf2(float a, float b) {
    __nv_bfloat162 t = __floats2bfloat162_rn(a, b);
    return *reinterpret_cast<u32*>(&t);
}

#define SW128(off) ((off) ^ (((off) >> 3) & 0x70))

// ---- Ampere-style async copy + ldmatrix + mma.sync (all legal on sm_103) ----
__device__ __forceinline__ void cpa16(u32 dst, const void* src, bool ok) {
    int sz = ok ? 16 : 0;
    asm volatile("cp.async.cg.shared.global [%0], [%1], 16, %2;"
                 :: "r"(dst), "l"(src), "r"(sz) : "memory");
}
__device__ __forceinline__ void cpa_commit() {
    asm volatile("cp.async.commit_group;" ::: "memory");
}
template<int N>
__device__ __forceinline__ void cpa_wait() {
    asm volatile("cp.async.wait_group %0;" :: "n"(N) : "memory");
}
__device__ __forceinline__ void ldsm_x4(u32* r, u32 addr) {
    asm volatile("ldmatrix.sync.aligned.m8n8.x4.shared.b16 {%0,%1,%2,%3}, [%4];"
                 : "=r"(r[0]), "=r"(r[1]), "=r"(r[2]), "=r"(r[3]) : "r"(addr));
}
__device__ __forceinline__ void mma16816(float* c, const u32* a, const u32* b) {
    asm volatile(
        "mma.sync.aligned.m16n8k16.row.col.f32.bf16.bf16.f32 "
        "{%0,%1,%2,%3}, {%4,%5,%6,%7}, {%8,%9}, {%0,%1,%2,%3};"
        : "+f"(c[0]), "+f"(c[1]), "+f"(c[2]), "+f"(c[3])
        : "r"(a[0]), "r"(a[1]), "r"(a[2]), "r"(a[3]), "r"(b[0]), "r"(b[1]));
}

// ============================================================================
// Kernel 0: prep — split/scale encode weights into pre-swizzled bf16 hi/lo
// tiles per tap (oc padded 100->128 with zeros), and BN shifts.
// ============================================================================
__global__ __launch_bounds__(256) void prep_kernel(
    const float* __restrict__ Wenc, const float* __restrict__ encb,
    const float* __restrict__ gamma, const float* __restrict__ beta,
    const float* __restrict__ mean,  const float* __restrict__ var)
{
    int t = blockIdx.x*256 + threadIdx.x;
    if (t < 128) {
        if (t < 100) {
            float inv = gamma[t] * rsqrtf(var[t] + 1e-5f);
            g_shift[t] = beta[t] - mean[t]*inv + encb[t]*inv;
        } else g_shift[t] = 0.f;
    }
    if (t >= 9*128*64) return;
    int tap = t >> 13;
    int rem = t & 8191;
    int oc  = rem >> 6;
    int ic  = rem & 63;
    float w = 0.f;
    if (oc < 100) {
        float inv = gamma[oc] * rsqrtf(var[oc] + 1e-5f);
        w = Wenc[(oc*64 + ic)*9 + tap] * inv;
    }
    __nv_bfloat16 h = __float2bfloat16(w);
    __nv_bfloat16 l = __float2bfloat16(w - __bfloat162float(h));
    u32 byteoff = (u32)(oc*128 + ic*2);
    u32 sw = SW128(byteoff);
    g_whi[tap*8192 + (sw >> 1)] = h;
    g_wlo[tap*8192 + (sw >> 1)] = l;
}

// ============================================================================
// Kernel 1: compress = 1x1 conv (64->64) + BN + ReLU -> NHWC bf16 hi/lo
// ============================================================================
__global__ __launch_bounds__(256) void compress_kernel(
    const float* __restrict__ X, const float* __restrict__ Wc,
    const float* __restrict__ gamma, const float* __restrict__ beta,
    const float* __restrict__ mean,  const float* __restrict__ var)
{
    __shared__ __align__(16) float ws[64*16];   // [ic][oc]
    __shared__ float sc[16], bs[16];
    int tid = threadIdx.x;
    int q   = blockIdx.y;           // oc quarter

    for (int t = tid; t < 1024; t += 256) {
        int oc = t >> 6, ic = t & 63;
        ws[ic*16 + oc] = Wc[(q*16 + oc)*64 + ic];
    }
    if (tid < 16) {
        int oc = q*16 + tid;
        float inv = gamma[oc] * rsqrtf(var[oc] + 1e-5f);
        sc[tid] = inv;
        bs[tid] = beta[oc] - mean[oc]*inv;
    }
    __syncthreads();

    int b = blockIdx.z;
    int p = ((blockIdx.x << 8) + tid) << 1;       // even pixel index
    const float2* Xb = reinterpret_cast<const float2*>(X + b*CC*HWSZ + p);

    u64 acc0[8], acc1[8];
#pragma unroll
    for (int i = 0; i < 8; i++) { acc0[i] = 0ULL; acc1[i] = 0ULL; }

    for (int ic0 = 0; ic0 < 64; ic0 += 8) {
        float2 xv[8];
#pragma unroll
        for (int u = 0; u < 8; u++) xv[u] = Xb[(ic0 + u)*(HWSZ/2)];
#pragma unroll
        for (int u = 0; u < 8; u++) {
            int ic = ic0 + u;
            u64 xa = pk2(xv[u].x, xv[u].x);
            u64 xc = pk2(xv[u].y, xv[u].y);
            const ulonglong2* w2 = reinterpret_cast<const ulonglong2*>(ws + (ic << 4));
#pragma unroll
            for (int m = 0; m < 4; m++) {
                ulonglong2 w = w2[m];
                acc0[2*m]   = fma2(xa, w.x, acc0[2*m]);
                acc0[2*m+1] = fma2(xa, w.y, acc0[2*m+1]);
                acc1[2*m]   = fma2(xc, w.x, acc1[2*m]);
                acc1[2*m+1] = fma2(xc, w.y, acc1[2*m+1]);
            }
        }
    }

    // BN + ReLU + bf16 hi/lo split, NHWC store
    u32 uh[16], ul[16];       // [pixel(2)][ch-pair(8)]
#pragma unroll
    for (int k = 0; k < 8; k++) {
        float2 f0 = up2(acc0[k]);
        float2 f1 = up2(acc1[k]);
        int oc = 2*k;
        float v00 = fmaxf(f0.x*sc[oc]   + bs[oc],   0.f);
        float v01 = fmaxf(f0.y*sc[oc+1] + bs[oc+1], 0.f);
        float v10 = fmaxf(f1.x*sc[oc]   + bs[oc],   0.f);
        float v11 = fmaxf(f1.y*sc[oc+1] + bs[oc+1], 0.f);
        float h00 = __bfloat162float(__float2bfloat16(v00));
        float h01 = __bfloat162float(__float2bfloat16(v01));
        float h10 = __bfloat162float(__float2bfloat16(v10));
        float h11 = __bfloat162float(__float2bfloat16(v11));
        uh[k]   = pack_bf2(v00, v01);
        ul[k]   = pack_bf2(v00 - h00, v01 - h01);
        uh[8+k] = pack_bf2(v10, v11);
        ul[8+k] = pack_bf2(v10 - h10, v11 - h11);
    }
    size_t base = ((size_t)b*HWSZ + p)*64 + q*16;    // bf16 elements
    const uint4* sh_ = reinterpret_cast<const uint4*>(uh);
    const uint4* sl_ = reinterpret_cast<const uint4*>(ul);
    *reinterpret_cast<uint4*>(g_chi + base)      = sh_[0];
    *reinterpret_cast<uint4*>(g_chi + base + 8)  = sh_[1];
    *reinterpret_cast<uint4*>(g_chi + base + 64) = sh_[2];
    *reinterpret_cast<uint4*>(g_chi + base + 72) = sh_[3];
    *reinterpret_cast<uint4*>(g_clo + base)      = sl_[0];
    *reinterpret_cast<uint4*>(g_clo + base + 8)  = sl_[1];
    *reinterpret_cast<uint4*>(g_clo + base + 64) = sl_[2];
    *reinterpret_cast<uint4*>(g_clo + base + 72) = sl_[3];
}

// ============================================================================
// Kernel 2: encode as mma.sync GEMM (sm_80-class HMMA path).
// One block per (b, Y): D = 128 oc x 128 px, K = 9 taps x 64 ic x 3 hi/lo
// combos. cp.async double-buffered tap pipeline; ldmatrix + m16n8k16 bf16.
// B tile is stored [px][ic] row-major == KxN column-major, so B uses
// NON-trans ldmatrix (fragment: lane l -> n=l/4, k=2*(l%4)) — the round-7
// .trans variant was the correctness bug.
// Buffer layout (64KB each): Ahi 16K | Alo 16K | Bhi 16K | Blo 16K.
// ============================================================================
#define EBUF 65536
#define ESM_TOTAL (1024 + 2*EBUF)

__global__ __launch_bounds__(256) void encode_mma_kernel()
{
    extern __shared__ char dsm[];
    u32 sb = (smem_u32(dsm) + 1023) & ~1023u;
    int tid  = threadIdx.x;
    int wid  = tid >> 5, lane = tid & 31;
    int warpM = wid & 3;          // oc:  warpM*32
    int warpN = wid >> 2;         // px:  warpN*64
    int Y = blockIdx.x;
    int b = blockIdx.y;

    // ---- staging lambda: tap -> buffer (16 cp.async of 16B per thread) ----
    auto stage = [&](int tap, u32 bufb) {
        // A: straight copy of pre-swizzled tiles
        const uint4* sAh = reinterpret_cast<const uint4*>(g_whi + tap*8192);
        const uint4* sAl = reinterpret_cast<const uint4*>(g_wlo + tap*8192);
#pragma unroll
        for (int k = 0; k < 4; k++) {
            int i = tid + k*256;                  // 0..1023
            cpa16(bufb + i*16,         sAh + i, true);
            cpa16(bufb + 16384 + i*16, sAl + i, true);
        }
        // B: gather NHWC rows with halo shift, zfill OOB
        int dy = tap / 3, dx = tap - dy*3;
        int ysrc = Y + dy - 1;
        bool yok = (unsigned)ysrc < 128u;
#pragma unroll
        for (int k = 0; k < 4; k++) {
            int i = tid + k*256;                  // 0..1023
            int px  = i >> 3;
            int seg = i & 7;
            int xsrc = px + dx - 1;
            bool ok = yok && ((unsigned)xsrc < 128u);
            size_t so = ok ? (((size_t)b*HWSZ + ysrc*128 + xsrc)*64 + seg*8) : 0;
            u32 dsto = SW128((u32)(px*128 + seg*16));
            cpa16(bufb + 32768 + dsto, g_chi + so, ok);
            cpa16(bufb + 49152 + dsto, g_clo + so, ok);
        }
        cpa_commit();
    };

    float c[2][8][4];
#pragma unroll
    for (int t = 0; t < 2; t++)
#pragma unroll
        for (int f = 0; f < 8; f++)
#pragma unroll
            for (int i = 0; i < 4; i++) c[t][f][i] = 0.f;

    // per-lane ldmatrix geometry (fixed across taps/ksteps)
    int rowA  = (lane & 15);
    int colA  = (lane >> 4) * 16;
    int rowB  = (lane & 7) + ((lane >> 4) & 1) * 8;
    int colB  = ((lane >> 3) & 1) * 16;

    stage(0, sb);

    for (int tap = 0; tap < 9; tap++) {
        u32 bufb = sb + (tap & 1)*EBUF;
        if (tap < 8) { stage(tap + 1, sb + ((tap + 1) & 1)*EBUF); cpa_wait<1>(); }
        else         { cpa_wait<0>(); }
        __syncthreads();

#pragma unroll
        for (int ks = 0; ks < 4; ks++) {
            u32 ah[2][4], al[2][4];
#pragma unroll
            for (int t = 0; t < 2; t++) {
                u32 off = SW128((u32)((warpM*32 + t*16 + rowA)*128 + ks*32 + colA));
                ldsm_x4(ah[t], bufb + off);
                ldsm_x4(al[t], bufb + 16384 + off);
            }
            u32 bh[8][2], bl[8][2];
#pragma unroll
            for (int fp = 0; fp < 4; fp++) {
                u32 off = SW128((u32)((warpN*64 + fp*16 + rowB)*128 + ks*32 + colB));
                u32 r[4];
                ldsm_x4(r, bufb + 32768 + off);      // non-trans (B is KxN col-major)
                bh[2*fp][0] = r[0]; bh[2*fp][1] = r[1];
                bh[2*fp+1][0] = r[2]; bh[2*fp+1][1] = r[3];
                ldsm_x4(r, bufb + 49152 + off);
                bl[2*fp][0] = r[0]; bl[2*fp][1] = r[1];
                bl[2*fp+1][0] = r[2]; bl[2*fp+1][1] = r[3];
            }
#pragma unroll
            for (int t = 0; t < 2; t++)
#pragma unroll
                for (int f = 0; f < 8; f++) {
                    mma16816(c[t][f], ah[t], bh[f]);
                    mma16816(c[t][f], ah[t], bl[f]);
                    mma16816(c[t][f], al[t], bh[f]);
                }
        }
        __syncthreads();
    }

    // ---- epilogue: transpose via smem, coalesced channel-last store ----
    float* strans = reinterpret_cast<float*>(dsm) +
                    ((sb - smem_u32(dsm)) >> 2);      // aligned base as float*
#pragma unroll
    for (int t = 0; t < 2; t++) {
        int row = warpM*32 + t*16 + (lane >> 2);
#pragma unroll
        for (int f = 0; f < 8; f++) {
            int col = warpN*64 + f*8 + (lane & 3)*2;
            strans[col*132 + row]         = c[t][f][0];
            strans[(col+1)*132 + row]     = c[t][f][1];
            strans[col*132 + row + 8]     = c[t][f][2];
            strans[(col+1)*132 + row + 8] = c[t][f][3];
        }
    }
    __syncthreads();

    float* ob = g_enc2 + ((size_t)b*HWSZ + Y*128)*ECP;
#pragma unroll
    for (int i = 0; i < 16; i++) {
        int idx = tid + i*256;          // 0..4095
        int px  = idx >> 5;
        int oc4 = idx & 31;
        float4 v  = *reinterpret_cast<const float4*>(strans + px*132 + oc4*4);
        float4 sh = *reinterpret_cast<const float4*>(g_shift + oc4*4);
        v.x += sh.x; v.y += sh.y; v.z += sh.z; v.w += sh.w;
        *reinterpret_cast<float4*>(ob + px*ECP + oc4*4) = v;
    }
}

// ============================================================================
// Kernel 3: pixel-shuffle + softmax(25) + CARAFE apply (row-pair quad reuse).
// Logits channel-last -> contiguous per-thread reads.
// ============================================================================
__global__ __launch_bounds__(256) void carafe_kernel(
    const float* __restrict__ X, float* __restrict__ out)
{
    __shared__ __align__(16) ulonglong2 stile[2][5*132];   // 21.1 KB
    int x = threadIdx.x;
    int Y = blockIdx.x;            // low-res row 0..127
    int b = blockIdx.y;
    int y0 = 2*Y;

    const float* encp = g_enc2 + ((size_t)b*HWSZ + Y*128 + (x >> 1))*ECP + (x & 1);

    float w0[25], w1[25];
    {
        float lg[25];
        float mx = -1e30f;
#pragma unroll
        for (int k = 0; k < 25; k++) { lg[k] = encp[k*4]; mx = fmaxf(mx, lg[k]); }
        float s = 0.f;
#pragma unroll
        for (int k = 0; k < 25; k++) { lg[k] = __expf(lg[k] - mx); s += lg[k]; }
        float inv = 1.f / s;
#pragma unroll
        for (int k = 0; k < 25; k++) w0[k] = lg[k]*inv;
    }
    {
        float lg[25];
        float mx = -1e30f;
#pragma unroll
        for (int k = 0; k < 25; k++) { lg[k] = encp[k*4 + 2]; mx = fmaxf(mx, lg[k]); }
        float s = 0.f;
#pragma unroll
        for (int k = 0; k < 25; k++) { lg[k] = __expf(lg[k] - mx); s += lg[k]; }
        float inv = 1.f / s;
#pragma unroll
        for (int k = 0; k < 25; k++) w1[k] = lg[k]*inv;
    }

    int q0 = Y - 2;
    int p2 = ((x - 4) >> 1) + 2;
    const float* Xb = X + b*CC*HWSZ;
    float* ob0 = out + (size_t)b*CC*(HO*WO) + y0*WO + x;
    float* ob1 = ob0 + WO;

    int  foff[3];
    bool fval[3];
#pragma unroll
    for (int k = 0; k < 3; k++) {
        int t = x + k*256;
        int i = t / 132;
        int cc = t - i*132 - 2;
        int r  = q0 + i;
        bool v = (t < 660) && ((unsigned)r < 128u) && ((unsigned)cc < 128u);
        fval[k] = v;
        foff[k] = v ? r*128 + cc : 0;
    }

    float rv[3][4];
#pragma unroll
    for (int k = 0; k < 3; k++) {
        const float* p = Xb + foff[k];
#pragma unroll
        for (int j = 0; j < 4; j++) rv[k][j] = fval[k] ? p[j*HWSZ] : 0.f;
    }
#pragma unroll
    for (int k = 0; k < 3; k++)
        if (x + k*256 < 660) {
            ulonglong2 pk;
            pk.x = pk2(rv[k][0], rv[k][1]);
            pk.y = pk2(rv[k][2], rv[k][3]);
            stile[0][x + k*256] = pk;
        }
    __syncthreads();

    for (int ci = 0; ci < 16; ci++) {
        int c = ci*4;
        if (ci + 1 < 16) {
#pragma unroll
            for (int k = 0; k < 3; k++) {
                const float* p = Xb + (c+4)*HWSZ + foff[k];
#pragma unroll
                for (int j = 0; j < 4; j++) rv[k][j] = fval[k] ? p[j*HWSZ] : 0.f;
            }
        }

        const ulonglong2* tb = stile[ci & 1];
        u64 r0a = 0ULL, r0b = 0ULL, r1a = 0ULL, r1b = 0ULL;
#pragma unroll
        for (int i = 0; i < 5; i++) {
            int base = i*132 + p2;
#pragma unroll
            for (int j = 0; j < 5; j++) {
                int k = i*5 + j;
                ulonglong2 sv = tb[base + j];
                u64 ww0 = pk2(w0[k], w0[k]);
                u64 ww1 = pk2(w1[k], w1[k]);
                r0a = fma2(ww0, sv.x, r0a);
                r0b = fma2(ww0, sv.y, r0b);
                r1a = fma2(ww1, sv.x, r1a);
                r1b = fma2(ww1, sv.y, r1b);
            }
        }
        float2 f0a = up2(r0a), f0b = up2(r0b);
        float2 f1a = up2(r1a), f1b = up2(r1b);
        ob0[c*(HO*WO)]     = f0a.x;
        ob0[(c+1)*(HO*WO)] = f0a.y;
        ob0[(c+2)*(HO*WO)] = f0b.x;
        ob0[(c+3)*(HO*WO)] = f0b.y;
        ob1[c*(HO*WO)]     = f1a.x;
        ob1[(c+1)*(HO*WO)] = f1a.y;
        ob1[(c+2)*(HO*WO)] = f1b.x;
        ob1[(c+3)*(HO*WO)] = f1b.y;

        if (ci + 1 < 16) {
            ulonglong2* buf = stile[(ci+1) & 1];
#pragma unroll
            for (int k = 0; k < 3; k++)
                if (x + k*256 < 660) {
                    ulonglong2 pk;
                    pk.x = pk2(rv[k][0], rv[k][1]);
                    pk.y = pk2(rv[k][2], rv[k][3]);
                    buf[x + k*256] = pk;
                }
        }
        __syncthreads();
    }
}

// ============================================================================
extern "C" void kernel_launch(void* const* d_in, const int* in_sizes, int n_in,
                              void* d_out, int out_size)
{
    const float* X          = (const float*)d_in[0];
    const float* comp_w     = (const float*)d_in[1];
    const float* comp_gamma = (const float*)d_in[2];
    const float* comp_beta  = (const float*)d_in[3];
    const float* comp_mean  = (const float*)d_in[4];
    const float* comp_var   = (const float*)d_in[5];
    const float* enc_w      = (const float*)d_in[6];
    const float* enc_b      = (const float*)d_in[7];
    const float* enc_gamma  = (const float*)d_in[8];
    const float* enc_beta   = (const float*)d_in[9];
    const float* enc_mean   = (const float*)d_in[10];
    const float* enc_var    = (const float*)d_in[11];
    float* out = (float*)d_out;

    cudaFuncSetAttribute(encode_mma_kernel,
                         cudaFuncAttributeMaxDynamicSharedMemorySize, ESM_TOTAL);

    prep_kernel<<<288, 256>>>(enc_w, enc_b, enc_gamma, enc_beta, enc_mean, enc_var);
    compress_kernel<<<dim3(32, 4, BB), 256>>>(X, comp_w, comp_gamma, comp_beta,
                                              comp_mean, comp_var);
    encode_mma_kernel<<<dim3(HH, BB), 256, ESM_TOTAL>>>();
    carafe_kernel<<<dim3(HH, BB), 256>>>(X, out);
}